// round 15
// baseline (speedup 1.0000x reference)
#include <cuda_runtime.h>
#include <math.h>

#define BB 4
#define NN 8192
#define KNB 9
#define CH 7
#define BNK (BB*NN*KNB)
#define BN_EPS 1e-5f
#define NEGINF (-3.4e38f)
#define NCELL 512              // 8x8x8 grid
#define GSZ 16                 // points per bound-group
#define GPB (NN/GSZ)           // 512 groups per batch

// scratch (allocation-free)
__device__ float g_feat[CH * BNK];
__device__ float g_acc[28];
__device__ float4 g_spts[BB * NN];   // sorted (x,y,z,|c|^2)
__device__ int    g_sidx[BB * NN];   // original index of sorted point
__device__ float4 g_sph[BB * GPB];   // per-group bounding sphere (cx,cy,cz,r)

__global__ void k_zero() {
    int t = threadIdx.x;
    if (t < 28) g_acc[t] = 0.f;
}

// ---------------------------------------------------------------------------
// k_sort: per-batch spatial counting sort into 8^3 cells + group spheres
// ---------------------------------------------------------------------------
__global__ __launch_bounds__(1024) void k_sort(const float* __restrict__ x) {
    const int b = blockIdx.x;
    const int tid = threadIdx.x;
    const float* xb = x + (size_t)b * NN * 3;

    __shared__ float wmn[32][3], wmx[32][3];
    __shared__ float s_min[3], s_inv[3];
    __shared__ int hist[NCELL];
    __shared__ int incl[NCELL];

    // min/max reduce
    float mn0=1e30f,mn1=1e30f,mn2=1e30f,mx0=-1e30f,mx1=-1e30f,mx2=-1e30f;
    for (int i = tid; i < NN; i += 1024) {
        float a=xb[i*3+0], c=xb[i*3+1], d=xb[i*3+2];
        mn0=fminf(mn0,a); mx0=fmaxf(mx0,a);
        mn1=fminf(mn1,c); mx1=fmaxf(mx1,c);
        mn2=fminf(mn2,d); mx2=fmaxf(mx2,d);
    }
    for (int off=16; off; off>>=1) {
        mn0=fminf(mn0,__shfl_xor_sync(~0u,mn0,off)); mx0=fmaxf(mx0,__shfl_xor_sync(~0u,mx0,off));
        mn1=fminf(mn1,__shfl_xor_sync(~0u,mn1,off)); mx1=fmaxf(mx1,__shfl_xor_sync(~0u,mx1,off));
        mn2=fminf(mn2,__shfl_xor_sync(~0u,mn2,off)); mx2=fmaxf(mx2,__shfl_xor_sync(~0u,mx2,off));
    }
    int w = tid >> 5, lane = tid & 31;
    if (lane == 0) {
        wmn[w][0]=mn0; wmn[w][1]=mn1; wmn[w][2]=mn2;
        wmx[w][0]=mx0; wmx[w][1]=mx1; wmx[w][2]=mx2;
    }
    __syncthreads();
    if (w == 0) {
        float a0=wmn[lane][0], a1=wmn[lane][1], a2=wmn[lane][2];
        float b0=wmx[lane][0], b1=wmx[lane][1], b2=wmx[lane][2];
        for (int off=16; off; off>>=1) {
            a0=fminf(a0,__shfl_xor_sync(~0u,a0,off)); b0=fmaxf(b0,__shfl_xor_sync(~0u,b0,off));
            a1=fminf(a1,__shfl_xor_sync(~0u,a1,off)); b1=fmaxf(b1,__shfl_xor_sync(~0u,b1,off));
            a2=fminf(a2,__shfl_xor_sync(~0u,a2,off)); b2=fmaxf(b2,__shfl_xor_sync(~0u,b2,off));
        }
        if (lane == 0) {
            s_min[0]=a0; s_min[1]=a1; s_min[2]=a2;
            s_inv[0]=8.0f/fmaxf(b0-a0,1e-20f);
            s_inv[1]=8.0f/fmaxf(b1-a1,1e-20f);
            s_inv[2]=8.0f/fmaxf(b2-a2,1e-20f);
        }
    }
    for (int i = tid; i < NCELL; i += 1024) hist[i] = 0;
    __syncthreads();

    // histogram
    for (int i = tid; i < NN; i += 1024) {
        int cx = min(7, max(0, (int)((xb[i*3+0]-s_min[0])*s_inv[0])));
        int cy = min(7, max(0, (int)((xb[i*3+1]-s_min[1])*s_inv[1])));
        int cz = min(7, max(0, (int)((xb[i*3+2]-s_min[2])*s_inv[2])));
        atomicAdd(&hist[cx + 8*cy + 64*cz], 1);
    }
    __syncthreads();

    // exclusive scan of hist (Hillis-Steele)
    int v = (tid < NCELL) ? hist[tid] : 0;
    if (tid < NCELL) incl[tid] = v;
    __syncthreads();
    for (int off = 1; off < NCELL; off <<= 1) {
        int t2 = 0;
        if (tid < NCELL && tid >= off) t2 = incl[tid-off];
        __syncthreads();
        if (tid < NCELL) incl[tid] += t2;
        __syncthreads();
    }
    if (tid < NCELL) hist[tid] = incl[tid] - v;   // hist = scatter cursor
    __syncthreads();

    // scatter
    for (int i = tid; i < NN; i += 1024) {
        float px=xb[i*3+0], py=xb[i*3+1], pz=xb[i*3+2];
        int cx = min(7, max(0, (int)((px-s_min[0])*s_inv[0])));
        int cy = min(7, max(0, (int)((py-s_min[1])*s_inv[1])));
        int cz = min(7, max(0, (int)((pz-s_min[2])*s_inv[2])));
        int pos = atomicAdd(&hist[cx + 8*cy + 64*cz], 1);
        float wq = fmaf(pz, pz, fmaf(py, py, px*px));   // same seq as query xsq
        g_spts[b*NN + pos] = make_float4(px, py, pz, wq);
        g_sidx[b*NN + pos] = i;
    }
    __syncthreads();

    // per-group bounding spheres (box center + half-diagonal)
    for (int g = tid; g < GPB; g += 1024) {
        float mnx=1e30f,mny=1e30f,mnz=1e30f,mxx=-1e30f,mxy=-1e30f,mxz=-1e30f;
        for (int u = 0; u < GSZ; u++) {
            float4 p = g_spts[b*NN + g*GSZ + u];
            mnx=fminf(mnx,p.x); mxx=fmaxf(mxx,p.x);
            mny=fminf(mny,p.y); mxy=fmaxf(mxy,p.y);
            mnz=fminf(mnz,p.z); mxz=fmaxf(mxz,p.z);
        }
        float cx=0.5f*(mnx+mxx), cy=0.5f*(mny+mxy), cz=0.5f*(mnz+mxz);
        float dx=mxx-cx, dy=mxy-cy, dz=mxz-cz;
        float r = sqrtf(dx*dx + dy*dy + dz*dz) + 1e-5f;
        g_sph[b*GPB + g] = make_float4(cx, cy, cz, r);
    }
}

// Parallel-select sorted insert with compound (d desc, j asc) predicate:
// result is the exact jax.lax.top_k list regardless of insertion order.
// d==NEGINF (sentinel) is a no-op (idx entries are either -1 or real j>=0;
// finite candidates never equal NEGINF).
__device__ __forceinline__ void ins10m(float d, int j, float dst[10], int idx[10]) {
    bool p[10];
#pragma unroll
    for (int k = 0; k < 10; k++)
        p[k] = (d > dst[k]) || (d == dst[k] && j < idx[k]);
#pragma unroll
    for (int k = 9; k >= 1; k--) {
        dst[k] = p[k] ? (p[k-1] ? dst[k-1] : d) : dst[k];
        idx[k] = p[k] ? (p[k-1] ? idx[k-1] : j) : idx[k];
    }
    dst[0] = p[0] ? d : dst[0];
    idx[0] = p[0] ? j : idx[0];
}

// ---------------------------------------------------------------------------
// k_knn: grid-pruned exact top-10 + umbrella geometry + linear1 + BN1 stats.
// Threads map to SORTED points; warp scans groups wrapped from its own group.
// ---------------------------------------------------------------------------
__global__ __launch_bounds__(256) void k_knn(const float* __restrict__ x,
                                             const float* __restrict__ w1) {
    __shared__ float4 sph[GPB];         // 8 KB sphere table
    __shared__ float s_w1[49];
    __shared__ float s_acc[14];

    const int tid = threadIdx.x;
    const int b = blockIdx.x >> 5;                  // 32 blocks per batch
    const int p = (blockIdx.x & 31) * 256 + tid;    // sorted position
    const float* xb = x + (size_t)b * NN * 3;
    const float4* sp = g_spts + b * NN;
    const int* sidx = g_sidx + b * NN;

    if (tid < 49) s_w1[tid] = w1[tid];
    if (tid < 14) s_acc[tid] = 0.f;
    for (int i = tid; i < GPB; i += 256) sph[i] = g_sph[b*GPB + i];

    const float4 me = sp[p];
    const int n = sidx[p];
    __syncthreads();

    const float x0 = me.x, x1 = me.y, x2 = me.z;
    const float xsqi = me.w;

    float dst[10]; int idx[10];
#pragma unroll
    for (int k = 0; k < 10; k++) { dst[k] = NEGINF; idx[k] = -1; }
    float thr = NEGINF;
    float rootthr = 1.8e19f;            // ~sqrt(-NEGINF): pass everything

    const int g0 = (blockIdx.x & 31) * 16 + ((tid >> 5) << 1);  // warp base group
    for (int gg = 0; gg < GPB; gg++) {
        const int g = (g0 + gg) & (GPB - 1);
        float4 S = sph[g];
        float ddx = x0 - S.x, ddy = x1 - S.y, ddz = x2 - S.z;
        float D2 = fmaf(ddz, ddz, fmaf(ddy, ddy, ddx*ddx));
        float tb = S.w + rootthr + 1e-2f;       // conservative slack >> fp error
        bool nearg = D2 < tb * tb;
        if (__any_sync(0xffffffffu, nearg)) {
            const float4* cp = sp + g * GSZ;
            const int* ip = sidx + g * GSZ;
#pragma unroll
            for (int h = 0; h < 2; h++) {
                float dv[8];
#pragma unroll
                for (int u = 0; u < 8; u++) {
                    float4 s = cp[h*8 + u];        // uniform LDG, L1-hot
                    float t = x0 * s.x;
                    t = fmaf(x1, s.y, t);
                    t = fmaf(x2, s.z, t);
                    dv[u] = fmaf(2.0f, t, -xsqi) - s.w;   // exact ref rounding
                }
                float m0 = fmaxf(fmaxf(dv[0], dv[1]), fmaxf(dv[2], dv[3]));
                float m1 = fmaxf(fmaxf(dv[4], dv[5]), fmaxf(dv[6], dv[7]));
                if (__any_sync(0xffffffffu, fmaxf(m0, m1) > thr)) {
                    unsigned pb = 0u;
#pragma unroll
                    for (int u = 0; u < 8; u++)
                        pb |= dv[u] > thr ? (1u << u) : 0u;
                    unsigned anyb = __reduce_or_sync(0xffffffffu, pb);
#pragma unroll
                    for (int u = 0; u < 8; u++) {
                        if (anyb & (1u << u)) {
                            ins10m((pb >> u) & 1u ? dv[u] : NEGINF,
                                   ip[h*8 + u], dst, idx);
                        }
                    }
                    thr = dst[9];
                    rootthr = (thr == NEGINF) ? 1.8e19f : sqrtf(-thr);
                }
            }
        }
    }

    // --- umbrella geometry on the 9 non-self neighbors (idx[1..9]) ---
    float vx[9], vy[9], vz[9], ph[9];
#pragma unroll
    for (int k = 0; k < 9; k++) {
        int j = idx[k+1];
        float ax = xb[j*3+0] - x0;
        float ay = xb[j*3+1] - x1;
        float az = xb[j*3+2] - x2;
        vx[k] = ax; vy[k] = ay; vz[k] = az;
        ph[k] = atan2f(ay, ax);
    }
#pragma unroll
    for (int a = 0; a < 8; a++) {
#pragma unroll
        for (int c = 0; c < 8 - a; c++) {
            if (ph[c] > ph[c+1]) {
                float t;
                t = ph[c]; ph[c] = ph[c+1]; ph[c+1] = t;
                t = vx[c]; vx[c] = vx[c+1]; vx[c+1] = t;
                t = vy[c]; vy[c] = vy[c+1]; vy[c+1] = t;
                t = vz[c]; vz[c] = vz[c+1]; vz[c+1] = t;
            }
        }
    }
    float c0x = vy[0]*vz[1] - vz[0]*vy[1] + 1e-5f;
    const float mask = (c0x > 0.f) ? 1.f : -1.f;

    float lsum[7], lsq[7];
#pragma unroll
    for (int o = 0; o < 7; o++) { lsum[o] = 0.f; lsq[o] = 0.f; }

    const int bnkBase = (b * NN + n) * KNB;
#pragma unroll
    for (int k = 0; k < 9; k++) {
        const int k2 = (k + 1 == 9) ? 0 : k + 1;
        float ax = vx[k],  ay = vy[k],  az = vz[k];
        float bx = vx[k2], by = vy[k2], bz = vz[k2];
        float cx = 0.5f*(ax+bx), cy = 0.5f*(ay+by), cz = 0.5f*(az+bz);
        float ux = ay*bz - az*by + 1e-5f;
        float uy = az*bx - ax*bz + 1e-5f;
        float uz = ax*by - ay*bx + 1e-5f;
        float inv = rsqrtf(ux*ux + uy*uy + uz*uz) * mask;
        ux *= inv; uy *= inv; uz *= inv;
        float pos = (cx*ux + cy*uy + cz*uz) * 0.57735026918962576f;
        float f[7] = {cx, cy, cz, ux, uy, uz, pos};
#pragma unroll
        for (int o = 0; o < 7; o++) {
            float h = 0.f;
#pragma unroll
            for (int c = 0; c < 7; c++) h = fmaf(f[c], s_w1[o*7+c], h);
            g_feat[o*BNK + bnkBase + k] = h;
            lsum[o] += h;
            lsq[o]   = fmaf(h, h, lsq[o]);
        }
    }

    const int lane = tid & 31;
#pragma unroll
    for (int o = 0; o < 7; o++) {
        float s = lsum[o], q = lsq[o];
        for (int off = 16; off; off >>= 1) {
            s += __shfl_xor_sync(0xffffffffu, s, off);
            q += __shfl_xor_sync(0xffffffffu, q, off);
        }
        if (lane == 0) { atomicAdd(&s_acc[o], s); atomicAdd(&s_acc[7+o], q); }
    }
    __syncthreads();
    if (tid < 14) atomicAdd(&g_acc[tid], s_acc[tid]);
}

// ---------------------------------------------------------------------------
// K2: BN1 + relu + linear2(+bias2), accumulate BN2 stats (in-place on g_feat)
// ---------------------------------------------------------------------------
__global__ __launch_bounds__(256) void k_mlp2(const float* __restrict__ gamma1,
                                              const float* __restrict__ beta1,
                                              const float* __restrict__ w2,
                                              const float* __restrict__ bias2) {
    __shared__ float s_w2[49], s_b2[7], s_scale[7], s_shift[7], s_acc[14];
    const int tid = threadIdx.x;
    if (tid < 49) s_w2[tid] = w2[tid];
    if (tid < 7) {
        s_b2[tid] = bias2[tid];
        float m = g_acc[tid] * (1.f / BNK);
        float v = g_acc[7+tid] * (1.f / BNK) - m*m;
        float sc = gamma1[tid] * rsqrtf(v + BN_EPS);
        s_scale[tid] = sc;
        s_shift[tid] = beta1[tid] - m*sc;
    }
    if (tid < 14) s_acc[tid] = 0.f;
    __syncthreads();

    const int bnk = blockIdx.x * 256 + tid;
    float r[7];
#pragma unroll
    for (int c = 0; c < 7; c++) {
        float h = g_feat[c*BNK + bnk];
        h = fmaf(h, s_scale[c], s_shift[c]);
        r[c] = fmaxf(h, 0.f);
    }
    float h[7], lsq[7];
#pragma unroll
    for (int o = 0; o < 7; o++) {
        float hh = s_b2[o];
#pragma unroll
        for (int c = 0; c < 7; c++) hh = fmaf(r[c], s_w2[o*7+c], hh);
        g_feat[o*BNK + bnk] = hh;
        h[o] = hh;
        lsq[o] = hh * hh;
    }
    const int lane = tid & 31;
#pragma unroll
    for (int o = 0; o < 7; o++) {
        float s = h[o], q = lsq[o];
        for (int off = 16; off; off >>= 1) {
            s += __shfl_xor_sync(0xffffffffu, s, off);
            q += __shfl_xor_sync(0xffffffffu, q, off);
        }
        if (lane == 0) { atomicAdd(&s_acc[o], s); atomicAdd(&s_acc[7+o], q); }
    }
    __syncthreads();
    if (tid < 14) atomicAdd(&g_acc[14+tid], s_acc[tid]);
}

// ---------------------------------------------------------------------------
// K3: BN2 + relu + linear3(+bias3) + maxpool over K, concat with x -> out
// ---------------------------------------------------------------------------
__global__ __launch_bounds__(256) void k_mlp3(const float* __restrict__ x,
                                              const float* __restrict__ gamma2,
                                              const float* __restrict__ beta2,
                                              const float* __restrict__ w3,
                                              const float* __restrict__ bias3,
                                              float* __restrict__ out) {
    __shared__ float s_w3[49], s_b3[7], s_scale[7], s_shift[7];
    const int tid = threadIdx.x;
    if (tid < 49) s_w3[tid] = w3[tid];
    if (tid < 7) {
        s_b3[tid] = bias3[tid];
        float m = g_acc[14+tid] * (1.f / BNK);
        float v = g_acc[21+tid] * (1.f / BNK) - m*m;
        float sc = gamma2[tid] * rsqrtf(v + BN_EPS);
        s_scale[tid] = sc;
        s_shift[tid] = beta2[tid] - m*sc;
    }
    __syncthreads();

    const int bn = blockIdx.x * 256 + tid;
    float best[7];
#pragma unroll
    for (int o = 0; o < 7; o++) best[o] = NEGINF;

#pragma unroll
    for (int k = 0; k < 9; k++) {
        float r[7];
#pragma unroll
        for (int c = 0; c < 7; c++) {
            float h = g_feat[c*BNK + bn*KNB + k];
            h = fmaf(h, s_scale[c], s_shift[c]);
            r[c] = fmaxf(h, 0.f);
        }
#pragma unroll
        for (int o = 0; o < 7; o++) {
            float h = s_b3[o];
#pragma unroll
            for (int c = 0; c < 7; c++) h = fmaf(r[c], s_w3[o*7+c], h);
            best[o] = fmaxf(best[o], h);
        }
    }
    out[bn*10+0] = x[bn*3+0];
    out[bn*10+1] = x[bn*3+1];
    out[bn*10+2] = x[bn*3+2];
#pragma unroll
    for (int o = 0; o < 7; o++) out[bn*10+3+o] = best[o];
}

extern "C" void kernel_launch(void* const* d_in, const int* in_sizes, int n_in,
                              void* d_out, int out_size) {
    const float* x      = (const float*)d_in[0];
    const float* w1     = (const float*)d_in[1];
    const float* gamma1 = (const float*)d_in[2];
    const float* beta1  = (const float*)d_in[3];
    const float* w2     = (const float*)d_in[4];
    const float* bias2  = (const float*)d_in[5];
    const float* gamma2 = (const float*)d_in[6];
    const float* beta2  = (const float*)d_in[7];
    const float* w3     = (const float*)d_in[8];
    const float* bias3  = (const float*)d_in[9];
    float* out = (float*)d_out;

    k_zero<<<1, 32>>>();
    k_sort<<<BB, 1024>>>(x);
    k_knn<<<BB * (NN / 256), 256>>>(x, w1);
    k_mlp2<<<BNK / 256, 256>>>(gamma1, beta1, w2, bias2);
    k_mlp3<<<(BB * NN) / 256, 256>>>(x, gamma2, beta2, w3, bias3, out);
}